// round 8
// baseline (speedup 1.0000x reference)
#include <cuda_runtime.h>
#include <cstdint>
#include <math.h>

// Attention_89627377533069
// memory [8,1024,2048] f32 (K | V), query [8,1024,1024] f32, seq_mask [8,1024] i32, b [1] f32
// out [8,1024,1024] f32.
// Scalar bias b is uniform over the softmax axis -> shift-invariant -> ignored (exact).

#define B_      8
#define S_      1024
#define H_      8
#define D_      128
#define UNITS_  1024
#define BM      128          // query rows per CTA
#define BN      64           // keys per tile
#define NWARP   8
#define NTHREAD 256
#define NITER   (S_ / BN)    // 16
#define KPAD    132          // K / V-staging smem row pitch (floats); 132 % 32 == 4
#define VTPAD   68           // Vt row pitch (floats); 68*4=272B, 272%128=16 -> conflict-free LDSM
#define PPAD    68           // P smem row pitch

// smem float offsets
#define K_OFF(s)  ((s) * (BN * KPAD))                 // stages: 0, 8448
#define V_OFF(s)  (2 * BN * KPAD + (s) * (BN * KPAD)) // 16896, 25344
#define M_OFF(s)  (4 * BN * KPAD + (s) * BN)          // 33792, 33856
#define VT_OFF    (4 * BN * KPAD + 2 * BN)            // 33920  (Vt: 128 x VTPAD)
#define P_BASE    (VT_OFF + D_ * VTPAD)               // 42624
#define SMEM_FLOATS (P_BASE + NWARP * 16 * PPAD)      // 51328
#define SMEM_BYTES  (SMEM_FLOATS * 4)                 // 205312

__device__ __forceinline__ uint32_t f2tf(float x) {
    uint32_t u;
    asm("cvt.rna.tf32.f32 %0, %1;" : "=r"(u) : "f"(x));
    return u;
}
__device__ __forceinline__ float f2tff(float x) {
    return __uint_as_float(f2tf(x));
}

__device__ __forceinline__ void mma8(float* c, const uint32_t* a, uint32_t b0, uint32_t b1) {
    asm volatile(
        "mma.sync.aligned.m16n8k8.row.col.f32.tf32.tf32.f32 "
        "{%0,%1,%2,%3}, {%4,%5,%6,%7}, {%8,%9}, {%0,%1,%2,%3};\n"
        : "+f"(c[0]), "+f"(c[1]), "+f"(c[2]), "+f"(c[3])
        : "r"(a[0]), "r"(a[1]), "r"(a[2]), "r"(a[3]), "r"(b0), "r"(b1));
}

// fp32-via-b16 ldmatrix: each 8x8 b16 matrix == an 8x4 fp32 block; lane i
// receives fp32 element (row = i/4, col = i%4) == tf32 mma fragment layout.
__device__ __forceinline__ void ldsm4(uint32_t& r0, uint32_t& r1, uint32_t& r2, uint32_t& r3,
                                      uint32_t addr) {
    asm volatile("ldmatrix.sync.aligned.m8n8.x4.shared.b16 {%0,%1,%2,%3}, [%4];\n"
                 : "=r"(r0), "=r"(r1), "=r"(r2), "=r"(r3)
                 : "r"(addr)
                 : "memory");
}

__device__ __forceinline__ void cp16(uint32_t s, const void* g) {
    asm volatile("cp.async.ca.shared.global [%0], [%1], 16;\n" :: "r"(s), "l"(g));
}
__device__ __forceinline__ void cp4(uint32_t s, const void* g) {
    asm volatile("cp.async.ca.shared.global [%0], [%1], 4;\n" :: "r"(s), "l"(g));
}

__global__ void __launch_bounds__(NTHREAD, 1)
attn_fa2_tf32_kernel(const float* __restrict__ memory,
                     const float* __restrict__ query,
                     const int*   __restrict__ seq_mask,
                     float*       __restrict__ out)
{
    extern __shared__ float sm[];
    const int tid  = threadIdx.x;
    const int warp = tid >> 5;
    const int lane = tid & 31;
    const int r = lane >> 2;    // fragment row group
    const int c = lane & 3;     // thread-in-group
    const int qtile = blockIdx.x;
    const int batch = blockIdx.y >> 3;
    const int head  = blockIdx.y & 7;

    const float* Kg = memory + (size_t)batch * S_ * 2048 + head * D_;
    const float* Vg = Kg + UNITS_;
    const int*   Mg = seq_mask + batch * S_;

    const uint32_t smbase = (uint32_t)__cvta_generic_to_shared(sm);

    // ---- per-lane LDSM address components ----
    // K B-frags (K tile row-major [key][d]):
    //   lanes 0-7 -> rows 0-7 col-lo, 8-15 -> rows 0-7 col-hi,
    //   16-23 -> rows 8-15 col-lo, 24-31 -> rows 8-15 col-hi  (per 16-key j-pair)
    const int kg = lane >> 3;
    const int kRow = ((kg >> 1) << 3) + (lane & 7);
    const int kCol = (kg & 1) << 2;
    const uint32_t kLaneOff = (uint32_t)(kRow * KPAD + kCol) * 4u;

    // V B-frags from Vt [d][key]: matrices m0/m1 = (b0,b1) of d-tile 2tp,
    //   m2/m3 = (b0,b1) of d-tile 2tp+1. Rows = d, float cols = key.
    const int vRow = (((lane >> 4) & 1) << 3) + (lane & 7);   // 0..15 within tp-pair
    const int vCol = ((lane >> 3) & 1) << 2;                  // 0 or 4 keys
    const uint32_t vLaneOff = (uint32_t)(vRow * VTPAD + vCol) * 4u;
    const uint32_t vtBase = smbase + (uint32_t)VT_OFF * 4u + vLaneOff;

    // P A-frags: m0 = rows 0-7 k-lo, m1 = rows 8-15 k-lo, m2 = rows 0-7 k-hi, m3 = rows 8-15 k-hi
    const int pRow = (((lane >> 3) & 1) << 3) + (lane & 7);
    const int pCol = (lane >> 4) << 2;
    const uint32_t pLaneOff = (uint32_t)(pRow * PPAD + pCol) * 4u;
    const uint32_t pWarpBase = smbase + (uint32_t)(P_BASE + warp * 16 * PPAD) * 4u + pLaneOff;

    // ---- Q fragments in registers (pre-scaled, rounded to tf32) ----
    uint32_t qa[16][4];
    {
        const float* Qp = query + ((size_t)batch * S_ + (size_t)qtile * BM + warp * 16) * UNITS_
                        + head * D_;
        const float scale = 0.08838834764831845f;  // 1/sqrt(128)
        #pragma unroll
        for (int kc = 0; kc < 16; kc++) {
            qa[kc][0] = f2tf(Qp[(size_t)r * UNITS_ + kc * 8 + c] * scale);
            qa[kc][1] = f2tf(Qp[(size_t)(r + 8) * UNITS_ + kc * 8 + c] * scale);
            qa[kc][2] = f2tf(Qp[(size_t)r * UNITS_ + kc * 8 + c + 4] * scale);
            qa[kc][3] = f2tf(Qp[(size_t)(r + 8) * UNITS_ + kc * 8 + c + 4] * scale);
        }
    }

    float oacc[16][4];
    #pragma unroll
    for (int t = 0; t < 16; t++) {
        oacc[t][0] = 0.f; oacc[t][1] = 0.f; oacc[t][2] = 0.f; oacc[t][3] = 0.f;
    }
    float m0 = -INFINITY, m1 = -INFINITY;
    float l0 = 0.f, l1 = 0.f;

    // ---- KV tile loader (into staging; one commit group per tile) ----
    auto issue = [&](int stage, int kt) {
        const int kb = kt * BN;
        #pragma unroll
        for (int i = 0; i < 8; i++) {
            int idx = tid + i * NTHREAD;            // 0..2047
            int row = idx >> 5;                      // 0..63
            int c4  = (idx & 31) * 4;                // 0..124 (floats)
            cp16(smbase + (uint32_t)(K_OFF(stage) + row * KPAD + c4) * 4,
                 Kg + (size_t)(kb + row) * 2048 + c4);
            cp16(smbase + (uint32_t)(V_OFF(stage) + row * KPAD + c4) * 4,
                 Vg + (size_t)(kb + row) * 2048 + c4);
        }
        if (tid < BN)
            cp4(smbase + (uint32_t)(M_OFF(stage) + tid) * 4, Mg + kb + tid);
        asm volatile("cp.async.commit_group;\n" ::: "memory");
    };

    issue(0, 0);

    float* Pw = sm + P_BASE + warp * 16 * PPAD;

    for (int kt = 0; kt < NITER; kt++) {
        const int cur = kt & 1;

        asm volatile("cp.async.wait_group 0;\n" ::: "memory");
        __syncthreads();   // (a) tile data visible; all warps past previous compute

        if (kt + 1 < NITER) issue(cur ^ 1, kt + 1);  // overlaps with prep + compute

        // ---- prep pass: K cvt-in-place; V transpose + cvt into Vt ----
        {
            float* Kc = sm + K_OFF(cur);
            #pragma unroll
            for (int i = 0; i < 8; i++) {
                int lin = tid + i * NTHREAD;
                int row = lin >> 5, c4 = (lin & 31) * 4;
                float4* p = (float4*)(Kc + row * KPAD + c4);
                float4 v = *p;
                v.x = f2tff(v.x); v.y = f2tff(v.y); v.z = f2tff(v.z); v.w = f2tff(v.w);
                *p = v;
            }
            const float* Vc = sm + V_OFF(cur);
            float* Vt = sm + VT_OFF;
            #pragma unroll
            for (int i = 0; i < 8; i++) {
                int lin = tid + i * NTHREAD;
                int key = lin & 63;          // varies across lanes -> conflict-free stores
                int d4  = (lin >> 6) * 4;    // constant per warp
                float4 v = *(const float4*)(Vc + key * KPAD + d4);
                Vt[(d4 + 0) * VTPAD + key] = f2tff(v.x);
                Vt[(d4 + 1) * VTPAD + key] = f2tff(v.y);
                Vt[(d4 + 2) * VTPAD + key] = f2tff(v.z);
                Vt[(d4 + 3) * VTPAD + key] = f2tff(v.w);
            }
        }
        __syncthreads();   // (b) prep visible to all warps

        const int* Ms = (const int*)(sm + M_OFF(cur));
        const uint32_t kStageBase = smbase + (uint32_t)K_OFF(cur) * 4u + kLaneOff;

        // ---- S = Q K^T  (tile [16 x 64] per warp); K already tf32 ----
        float sacc[8][4];
        #pragma unroll
        for (int j = 0; j < 8; j++) {
            sacc[j][0] = 0.f; sacc[j][1] = 0.f; sacc[j][2] = 0.f; sacc[j][3] = 0.f;
        }
        #pragma unroll
        for (int kc = 0; kc < 16; kc++) {
            #pragma unroll
            for (int p = 0; p < 4; p++) {
                uint32_t b0, b1, b2, b3;
                ldsm4(b0, b1, b2, b3,
                      kStageBase + (uint32_t)(p * 16 * KPAD + kc * 8) * 4u);
                mma8(sacc[2 * p],     qa[kc], b0, b1);
                mma8(sacc[2 * p + 1], qa[kc], b2, b3);
            }
        }

        // ---- key mask (additive -1e30) ----
        #pragma unroll
        for (int j = 0; j < 8; j++) {
            float a0 = Ms[j * 8 + 2 * c]     ? 0.f : -1e30f;
            float a1 = Ms[j * 8 + 2 * c + 1] ? 0.f : -1e30f;
            sacc[j][0] += a0; sacc[j][2] += a0;
            sacc[j][1] += a1; sacc[j][3] += a1;
        }

        // ---- online softmax ----
        float mx0 = -INFINITY, mx1 = -INFINITY;
        #pragma unroll
        for (int j = 0; j < 8; j++) {
            mx0 = fmaxf(mx0, fmaxf(sacc[j][0], sacc[j][1]));
            mx1 = fmaxf(mx1, fmaxf(sacc[j][2], sacc[j][3]));
        }
        mx0 = fmaxf(mx0, __shfl_xor_sync(0xffffffffu, mx0, 1));
        mx0 = fmaxf(mx0, __shfl_xor_sync(0xffffffffu, mx0, 2));
        mx1 = fmaxf(mx1, __shfl_xor_sync(0xffffffffu, mx1, 1));
        mx1 = fmaxf(mx1, __shfl_xor_sync(0xffffffffu, mx1, 2));

        float mn0 = fmaxf(m0, mx0), mn1 = fmaxf(m1, mx1);
        float al0 = __expf(m0 - mn0), al1 = __expf(m1 - mn1);
        m0 = mn0; m1 = mn1;

        float rs0 = 0.f, rs1 = 0.f;
        #pragma unroll
        for (int j = 0; j < 8; j++) {
            float p0 = f2tff(__expf(sacc[j][0] - mn0));
            float p1 = f2tff(__expf(sacc[j][1] - mn0));
            float p2 = f2tff(__expf(sacc[j][2] - mn1));
            float p3 = f2tff(__expf(sacc[j][3] - mn1));
            rs0 += p0 + p1;
            rs1 += p2 + p3;
            *(float2*)(Pw + r * PPAD + j * 8 + 2 * c)       = make_float2(p0, p1);
            *(float2*)(Pw + (r + 8) * PPAD + j * 8 + 2 * c) = make_float2(p2, p3);
        }
        rs0 += __shfl_xor_sync(0xffffffffu, rs0, 1);
        rs0 += __shfl_xor_sync(0xffffffffu, rs0, 2);
        rs1 += __shfl_xor_sync(0xffffffffu, rs1, 1);
        rs1 += __shfl_xor_sync(0xffffffffu, rs1, 2);
        l0 = l0 * al0 + rs0;
        l1 = l1 * al1 + rs1;

        #pragma unroll
        for (int t = 0; t < 16; t++) {
            oacc[t][0] *= al0; oacc[t][1] *= al0;
            oacc[t][2] *= al1; oacc[t][3] *= al1;
        }

        __syncwarp();   // P stores visible to own-warp ldmatrix

        // ---- O += P V  (all operands pre-rounded tf32; LDSM-only feed) ----
        #pragma unroll
        for (int kc = 0; kc < 8; kc++) {
            uint32_t pa[4];
            ldsm4(pa[0], pa[1], pa[2], pa[3], pWarpBase + (uint32_t)(kc * 8) * 4u);
            #pragma unroll
            for (int tp = 0; tp < 8; tp++) {
                uint32_t v0, v1, v2, v3;
                ldsm4(v0, v1, v2, v3, vtBase + (uint32_t)(tp * 16 * VTPAD + kc * 8) * 4u);
                mma8(oacc[2 * tp],     pa, v0, v1);
                mma8(oacc[2 * tp + 1], pa, v2, v3);
            }
        }
        // next iteration's sync (a) guards Vt/K/P reuse
    }

    // ---- epilogue: normalize + store ----
    const float li0 = 1.f / l0;
    const float li1 = 1.f / l1;
    float* Op = out + ((size_t)batch * S_ + (size_t)qtile * BM + warp * 16) * UNITS_ + head * D_;
    #pragma unroll
    for (int t = 0; t < 16; t++) {
        *(float2*)(Op + (size_t)r * UNITS_ + t * 8 + 2 * c) =
            make_float2(oacc[t][0] * li0, oacc[t][1] * li0);
        *(float2*)(Op + (size_t)(r + 8) * UNITS_ + t * 8 + 2 * c) =
            make_float2(oacc[t][2] * li1, oacc[t][3] * li1);
    }
}

extern "C" void kernel_launch(void* const* d_in, const int* in_sizes, int n_in,
                              void* d_out, int out_size)
{
    const float* memory = (const float*)d_in[0];
    const float* query  = (const float*)d_in[1];
    const int*   seqm   = (const int*)d_in[2];
    // d_in[3] (scalar bias b) is provably a no-op under softmax -> ignored.

    cudaFuncSetAttribute(attn_fa2_tf32_kernel,
                         cudaFuncAttributeMaxDynamicSharedMemorySize, SMEM_BYTES);

    dim3 grid(S_ / BM, B_ * H_);
    attn_fa2_tf32_kernel<<<grid, NTHREAD, SMEM_BYTES>>>(memory, query, seqm, (float*)d_out);
}

// round 9
// speedup vs baseline: 1.4759x; 1.4759x over previous
#include <cuda_runtime.h>
#include <cstdint>
#include <math.h>

// Attention_89627377533069
// memory [8,1024,2048] f32 (K | V), query [8,1024,1024] f32, seq_mask [8,1024] i32, b [1] f32
// out [8,1024,1024] f32.
// Scalar bias b is uniform over the softmax axis -> shift-invariant -> ignored (exact).

#define B_      8
#define S_      1024
#define H_      8
#define D_      128
#define UNITS_  1024
#define BM      128          // query rows per CTA
#define BN      64           // keys per tile
#define NWARP   8
#define NTHREAD 256
#define NITER   (S_ / BN)    // 16
#define KPAD    132          // K / V-staging smem row pitch (floats); 132 % 32 == 4
#define VTPAD   68           // Vt row pitch (floats); 68*4=272B, 272%128=16 -> conflict-free LDSM
#define PPAD    68           // P smem row pitch

// smem float offsets
#define K_OFF(s)  ((s) * (BN * KPAD))                 // stages: 0, 8448
#define V_OFF(s)  (2 * BN * KPAD + (s) * (BN * KPAD)) // 16896, 25344
#define M_OFF(s)  (4 * BN * KPAD + (s) * BN)          // 33792, 33856
#define VT_OFF    (4 * BN * KPAD + 2 * BN)            // 33920  (Vt: 128 x VTPAD)
#define P_BASE    (VT_OFF + D_ * VTPAD)               // 42624
#define SMEM_FLOATS (P_BASE + NWARP * 16 * PPAD)      // 51328
#define SMEM_BYTES  (SMEM_FLOATS * 4)                 // 205312

__device__ __forceinline__ uint32_t f2tf(float x) {
    uint32_t u;
    asm("cvt.rna.tf32.f32 %0, %1;" : "=r"(u) : "f"(x));
    return u;
}
__device__ __forceinline__ float f2tff(float x) {
    return __uint_as_float(f2tf(x));
}

__device__ __forceinline__ void mma8(float* c, const uint32_t* a, uint32_t b0, uint32_t b1) {
    asm volatile(
        "mma.sync.aligned.m16n8k8.row.col.f32.tf32.tf32.f32 "
        "{%0,%1,%2,%3}, {%4,%5,%6,%7}, {%8,%9}, {%0,%1,%2,%3};\n"
        : "+f"(c[0]), "+f"(c[1]), "+f"(c[2]), "+f"(c[3])
        : "r"(a[0]), "r"(a[1]), "r"(a[2]), "r"(a[3]), "r"(b0), "r"(b1));
}

// fp32-via-b16 ldmatrix: each 8x8 b16 matrix == an 8x4 fp32 block; lane i
// receives fp32 element (row = i/4, col = i%4) == tf32 mma fragment layout.
__device__ __forceinline__ void ldsm4(uint32_t& r0, uint32_t& r1, uint32_t& r2, uint32_t& r3,
                                      uint32_t addr) {
    asm volatile("ldmatrix.sync.aligned.m8n8.x4.shared.b16 {%0,%1,%2,%3}, [%4];\n"
                 : "=r"(r0), "=r"(r1), "=r"(r2), "=r"(r3)
                 : "r"(addr)
                 : "memory");
}

__device__ __forceinline__ void cp16(uint32_t s, const void* g) {
    asm volatile("cp.async.ca.shared.global [%0], [%1], 16;\n" :: "r"(s), "l"(g));
}
__device__ __forceinline__ void cp4(uint32_t s, const void* g) {
    asm volatile("cp.async.ca.shared.global [%0], [%1], 4;\n" :: "r"(s), "l"(g));
}

__global__ void __launch_bounds__(NTHREAD, 1)
attn_fa2_tf32_kernel(const float* __restrict__ memory,
                     const float* __restrict__ query,
                     const int*   __restrict__ seq_mask,
                     float*       __restrict__ out)
{
    extern __shared__ float sm[];
    const int tid  = threadIdx.x;
    const int warp = tid >> 5;
    const int lane = tid & 31;
    const int r = lane >> 2;    // fragment row group
    const int c = lane & 3;     // thread-in-group
    const int qtile = blockIdx.x;
    const int batch = blockIdx.y >> 3;
    const int head  = blockIdx.y & 7;

    const float* Kg = memory + (size_t)batch * S_ * 2048 + head * D_;
    const float* Vg = Kg + UNITS_;
    const int*   Mg = seq_mask + batch * S_;

    const uint32_t smbase = (uint32_t)__cvta_generic_to_shared(sm);

    // ---- per-lane LDSM address components ----
    // K B-frags (K tile row-major [key][d]):
    //   lanes 0-7 -> rows 0-7 col-lo, 8-15 -> rows 0-7 col-hi,
    //   16-23 -> rows 8-15 col-lo, 24-31 -> rows 8-15 col-hi  (per 16-key j-pair)
    const int kg = lane >> 3;
    const int kRow = ((kg >> 1) << 3) + (lane & 7);
    const int kCol = (kg & 1) << 2;
    const uint32_t kLaneOff = (uint32_t)(kRow * KPAD + kCol) * 4u;

    // V B-frags from Vt [d][key]: matrices m0/m1 = (b0,b1) of d-tile 2tp,
    //   m2/m3 = (b0,b1) of d-tile 2tp+1. Rows = d, float cols = key.
    const int vRow = (((lane >> 4) & 1) << 3) + (lane & 7);   // 0..15 within tp-pair
    const int vCol = ((lane >> 3) & 1) << 2;                  // 0 or 4 keys
    const uint32_t vLaneOff = (uint32_t)(vRow * VTPAD + vCol) * 4u;
    const uint32_t vtBase = smbase + (uint32_t)VT_OFF * 4u + vLaneOff;

    // P A-frags: m0 = rows 0-7 k-lo, m1 = rows 8-15 k-lo, m2 = rows 0-7 k-hi, m3 = rows 8-15 k-hi
    const int pRow = (((lane >> 3) & 1) << 3) + (lane & 7);
    const int pCol = (lane >> 4) << 2;
    const uint32_t pLaneOff = (uint32_t)(pRow * PPAD + pCol) * 4u;
    const uint32_t pWarpBase = smbase + (uint32_t)(P_BASE + warp * 16 * PPAD) * 4u + pLaneOff;

    // ---- Q fragments in registers (pre-scaled, rounded to tf32) ----
    uint32_t qa[16][4];
    {
        const float* Qp = query + ((size_t)batch * S_ + (size_t)qtile * BM + warp * 16) * UNITS_
                        + head * D_;
        const float scale = 0.08838834764831845f;  // 1/sqrt(128)
        #pragma unroll
        for (int kc = 0; kc < 16; kc++) {
            qa[kc][0] = f2tf(Qp[(size_t)r * UNITS_ + kc * 8 + c] * scale);
            qa[kc][1] = f2tf(Qp[(size_t)(r + 8) * UNITS_ + kc * 8 + c] * scale);
            qa[kc][2] = f2tf(Qp[(size_t)r * UNITS_ + kc * 8 + c + 4] * scale);
            qa[kc][3] = f2tf(Qp[(size_t)(r + 8) * UNITS_ + kc * 8 + c + 4] * scale);
        }
    }

    float oacc[16][4];
    #pragma unroll
    for (int t = 0; t < 16; t++) {
        oacc[t][0] = 0.f; oacc[t][1] = 0.f; oacc[t][2] = 0.f; oacc[t][3] = 0.f;
    }
    float m0 = -INFINITY, m1 = -INFINITY;
    float l0 = 0.f, l1 = 0.f;

    // ---- KV tile loader (into staging; one commit group per tile) ----
    auto issue = [&](int stage, int kt) {
        const int kb = kt * BN;
        #pragma unroll
        for (int i = 0; i < 8; i++) {
            int idx = tid + i * NTHREAD;            // 0..2047
            int row = idx >> 5;                      // 0..63
            int c4  = (idx & 31) * 4;                // 0..124 (floats)
            cp16(smbase + (uint32_t)(K_OFF(stage) + row * KPAD + c4) * 4,
                 Kg + (size_t)(kb + row) * 2048 + c4);
            cp16(smbase + (uint32_t)(V_OFF(stage) + row * KPAD + c4) * 4,
                 Vg + (size_t)(kb + row) * 2048 + c4);
        }
        if (tid < BN)
            cp4(smbase + (uint32_t)(M_OFF(stage) + tid) * 4, Mg + kb + tid);
        asm volatile("cp.async.commit_group;\n" ::: "memory");
    };

    issue(0, 0);

    float* Pw = sm + P_BASE + warp * 16 * PPAD;

    for (int kt = 0; kt < NITER; kt++) {
        const int cur = kt & 1;

        asm volatile("cp.async.wait_group 0;\n" ::: "memory");
        __syncthreads();   // (a) tile data visible; all warps past previous compute

        if (kt + 1 < NITER) issue(cur ^ 1, kt + 1);  // overlaps with prep + compute

        // ---- prep pass: K cvt-in-place; V transpose + cvt into Vt ----
        {
            float* Kc = sm + K_OFF(cur);
            #pragma unroll
            for (int i = 0; i < 8; i++) {
                int lin = tid + i * NTHREAD;
                int row = lin >> 5, c4 = (lin & 31) * 4;
                float4* p = (float4*)(Kc + row * KPAD + c4);
                float4 v = *p;
                v.x = f2tff(v.x); v.y = f2tff(v.y); v.z = f2tff(v.z); v.w = f2tff(v.w);
                *p = v;
            }
            const float* Vc = sm + V_OFF(cur);
            float* Vt = sm + VT_OFF;
            #pragma unroll
            for (int i = 0; i < 8; i++) {
                int lin = tid + i * NTHREAD;
                int key = lin & 63;          // varies across lanes -> conflict-free stores
                int d4  = (lin >> 6) * 4;    // constant per warp
                float4 v = *(const float4*)(Vc + key * KPAD + d4);
                Vt[(d4 + 0) * VTPAD + key] = f2tff(v.x);
                Vt[(d4 + 1) * VTPAD + key] = f2tff(v.y);
                Vt[(d4 + 2) * VTPAD + key] = f2tff(v.z);
                Vt[(d4 + 3) * VTPAD + key] = f2tff(v.w);
            }
        }
        __syncthreads();   // (b) prep visible to all warps

        const int* Ms = (const int*)(sm + M_OFF(cur));
        const uint32_t kStageBase = smbase + (uint32_t)K_OFF(cur) * 4u + kLaneOff;

        // ---- S = Q K^T  (tile [16 x 64] per warp); K already tf32 ----
        float sacc[8][4];
        #pragma unroll
        for (int j = 0; j < 8; j++) {
            sacc[j][0] = 0.f; sacc[j][1] = 0.f; sacc[j][2] = 0.f; sacc[j][3] = 0.f;
        }
        #pragma unroll
        for (int kc = 0; kc < 16; kc++) {
            #pragma unroll
            for (int p = 0; p < 4; p++) {
                uint32_t b0, b1, b2, b3;
                ldsm4(b0, b1, b2, b3,
                      kStageBase + (uint32_t)(p * 16 * KPAD + kc * 8) * 4u);
                mma8(sacc[2 * p],     qa[kc], b0, b1);
                mma8(sacc[2 * p + 1], qa[kc], b2, b3);
            }
        }

        // ---- key mask (additive -1e30) ----
        #pragma unroll
        for (int j = 0; j < 8; j++) {
            float a0 = Ms[j * 8 + 2 * c]     ? 0.f : -1e30f;
            float a1 = Ms[j * 8 + 2 * c + 1] ? 0.f : -1e30f;
            sacc[j][0] += a0; sacc[j][2] += a0;
            sacc[j][1] += a1; sacc[j][3] += a1;
        }

        // ---- online softmax ----
        float mx0 = -INFINITY, mx1 = -INFINITY;
        #pragma unroll
        for (int j = 0; j < 8; j++) {
            mx0 = fmaxf(mx0, fmaxf(sacc[j][0], sacc[j][1]));
            mx1 = fmaxf(mx1, fmaxf(sacc[j][2], sacc[j][3]));
        }
        mx0 = fmaxf(mx0, __shfl_xor_sync(0xffffffffu, mx0, 1));
        mx0 = fmaxf(mx0, __shfl_xor_sync(0xffffffffu, mx0, 2));
        mx1 = fmaxf(mx1, __shfl_xor_sync(0xffffffffu, mx1, 1));
        mx1 = fmaxf(mx1, __shfl_xor_sync(0xffffffffu, mx1, 2));

        float mn0 = fmaxf(m0, mx0), mn1 = fmaxf(m1, mx1);
        float al0 = __expf(m0 - mn0), al1 = __expf(m1 - mn1);
        m0 = mn0; m1 = mn1;

        float rs0 = 0.f, rs1 = 0.f;
        #pragma unroll
        for (int j = 0; j < 8; j++) {
            float p0 = f2tff(__expf(sacc[j][0] - mn0));
            float p1 = f2tff(__expf(sacc[j][1] - mn0));
            float p2 = f2tff(__expf(sacc[j][2] - mn1));
            float p3 = f2tff(__expf(sacc[j][3] - mn1));
            rs0 += p0 + p1;
            rs1 += p2 + p3;
            *(float2*)(Pw + r * PPAD + j * 8 + 2 * c)       = make_float2(p0, p1);
            *(float2*)(Pw + (r + 8) * PPAD + j * 8 + 2 * c) = make_float2(p2, p3);
        }
        rs0 += __shfl_xor_sync(0xffffffffu, rs0, 1);
        rs0 += __shfl_xor_sync(0xffffffffu, rs0, 2);
        rs1 += __shfl_xor_sync(0xffffffffu, rs1, 1);
        rs1 += __shfl_xor_sync(0xffffffffu, rs1, 2);
        l0 = l0 * al0 + rs0;
        l1 = l1 * al1 + rs1;

        #pragma unroll
        for (int t = 0; t < 16; t++) {
            oacc[t][0] *= al0; oacc[t][1] *= al0;
            oacc[t][2] *= al1; oacc[t][3] *= al1;
        }

        __syncwarp();   // P stores visible to own-warp ldmatrix

        // ---- O += P V  (all operands pre-rounded tf32; LDSM-only feed) ----
        #pragma unroll
        for (int kc = 0; kc < 8; kc++) {
            uint32_t pa[4];
            ldsm4(pa[0], pa[1], pa[2], pa[3], pWarpBase + (uint32_t)(kc * 8) * 4u);
            #pragma unroll
            for (int tp = 0; tp < 8; tp++) {
                uint32_t v0, v1, v2, v3;
                ldsm4(v0, v1, v2, v3, vtBase + (uint32_t)(tp * 16 * VTPAD + kc * 8) * 4u);
                mma8(oacc[2 * tp],     pa, v0, v1);
                mma8(oacc[2 * tp + 1], pa, v2, v3);
            }
        }
        // next iteration's sync (a) guards Vt/K/P reuse
    }

    // ---- epilogue: normalize + store ----
    const float li0 = 1.f / l0;
    const float li1 = 1.f / l1;
    float* Op = out + ((size_t)batch * S_ + (size_t)qtile * BM + warp * 16) * UNITS_ + head * D_;
    #pragma unroll
    for (int t = 0; t < 16; t++) {
        *(float2*)(Op + (size_t)r * UNITS_ + t * 8 + 2 * c) =
            make_float2(oacc[t][0] * li0, oacc[t][1] * li0);
        *(float2*)(Op + (size_t)(r + 8) * UNITS_ + t * 8 + 2 * c) =
            make_float2(oacc[t][2] * li1, oacc[t][3] * li1);
    }
}

extern "C" void kernel_launch(void* const* d_in, const int* in_sizes, int n_in,
                              void* d_out, int out_size)
{
    const float* memory = (const float*)d_in[0];
    const float* query  = (const float*)d_in[1];
    const int*   seqm   = (const int*)d_in[2];
    // d_in[3] (scalar bias b) is provably a no-op under softmax -> ignored.

    cudaFuncSetAttribute(attn_fa2_tf32_kernel,
                         cudaFuncAttributeMaxDynamicSharedMemorySize, SMEM_BYTES);

    dim3 grid(S_ / BM, B_ * H_);
    attn_fa2_tf32_kernel<<<grid, NTHREAD, SMEM_BYTES>>>(memory, query, seqm, (float*)d_out);
}